// round 3
// baseline (speedup 1.0000x reference)
#include <cuda_runtime.h>
#include <math.h>

#define MAX_NODES 50000
#define IN_DIM 100
#define HID 16
#define NC 40

// Scratch (no allocations allowed): Y = X@W1, Z1 = A@Y, Z2 = A@relu(Z1)
__device__ float g_Y [MAX_NODES * HID];
__device__ float g_Z1[MAX_NODES * HID];
__device__ float g_Z2[MAX_NODES * HID];

// ---------------------------------------------------------------------------
// Y[n, 0:16] = features[n, 0:100] @ W1[100, 16], one THREAD per node.
// 25x LDG.128 feature reads, 16 register accumulators, W1 staged in smem as
// float4 (broadcast LDS.128). Also zeroes Z1/Z2 rows (replaces zero_kernel;
// kernel boundary orders the zeroing before spmm's REDs).
// ---------------------------------------------------------------------------
__global__ void gemm1_kernel(const float* __restrict__ X,
                             const float* __restrict__ W1, int N) {
    __shared__ float4 w[IN_DIM * 4];                  // w[k*4+j4] = W1[k][4j4:4j4+4]
    for (int i = threadIdx.x; i < IN_DIM * 4; i += blockDim.x)
        w[i] = ((const float4*)W1)[i];
    __syncthreads();
    int n = blockIdx.x * blockDim.x + threadIdx.x;
    if (n >= N) return;

    const float4* xr = (const float4*)(X + (size_t)n * IN_DIM);  // 400B rows, 16B aligned
    float acc[HID];
#pragma unroll
    for (int j = 0; j < HID; j++) acc[j] = 0.f;

#pragma unroll 5
    for (int k4 = 0; k4 < IN_DIM / 4; k4++) {
        float4 f = __ldg(xr + k4);
        float fk[4] = {f.x, f.y, f.z, f.w};
#pragma unroll
        for (int kk = 0; kk < 4; kk++) {
            int k = k4 * 4 + kk;
#pragma unroll
            for (int j4 = 0; j4 < 4; j4++) {
                float4 wv = w[k * 4 + j4];
                acc[j4 * 4 + 0] += fk[kk] * wv.x;
                acc[j4 * 4 + 1] += fk[kk] * wv.y;
                acc[j4 * 4 + 2] += fk[kk] * wv.z;
                acc[j4 * 4 + 3] += fk[kk] * wv.w;
            }
        }
    }

    float4* yo = (float4*)(g_Y + (size_t)n * HID);
#pragma unroll
    for (int j4 = 0; j4 < 4; j4++)
        yo[j4] = make_float4(acc[j4*4+0], acc[j4*4+1], acc[j4*4+2], acc[j4*4+3]);

    // Zero the accumulator rows for this node (both layers).
    float4 z = make_float4(0.f, 0.f, 0.f, 0.f);
    float4* z1 = (float4*)(g_Z1 + (size_t)n * HID);
    float4* z2 = (float4*)(g_Z2 + (size_t)n * HID);
#pragma unroll
    for (int j4 = 0; j4 < 4; j4++) { z1[j4] = z; z2[j4] = z; }
}

// ---------------------------------------------------------------------------
// SpMM scatter: Z[dst] += val * (relu?)(X[src]), 16-dim rows.
// 2 edges per thread: indices via int2/float2 (3 vector loads per 2 edges vs
// 24 scalar loads in the 4-thread/edge scheme). Per edge: 4 independent
// LDG.128 gathers (L2-resident, 3.2MB table) + 4 red.global.add.v4.f32.
// ---------------------------------------------------------------------------
template <bool FIRST>
__device__ __forceinline__ void do_edge(const float* __restrict__ X,
                                        float* __restrict__ Z,
                                        int s, int d, float wv) {
    const float4* xp = (const float4*)(X + (size_t)s * HID);
    float4 x0 = __ldg(xp + 0), x1 = __ldg(xp + 1);
    float4 x2 = __ldg(xp + 2), x3 = __ldg(xp + 3);
    if (!FIRST) {  // fused relu on layer-2 gather
        x0.x=fmaxf(x0.x,0.f); x0.y=fmaxf(x0.y,0.f); x0.z=fmaxf(x0.z,0.f); x0.w=fmaxf(x0.w,0.f);
        x1.x=fmaxf(x1.x,0.f); x1.y=fmaxf(x1.y,0.f); x1.z=fmaxf(x1.z,0.f); x1.w=fmaxf(x1.w,0.f);
        x2.x=fmaxf(x2.x,0.f); x2.y=fmaxf(x2.y,0.f); x2.z=fmaxf(x2.z,0.f); x2.w=fmaxf(x2.w,0.f);
        x3.x=fmaxf(x3.x,0.f); x3.y=fmaxf(x3.y,0.f); x3.z=fmaxf(x3.z,0.f); x3.w=fmaxf(x3.w,0.f);
    }
    float* zp = Z + (size_t)d * HID;
    asm volatile("red.global.add.v4.f32 [%0], {%1, %2, %3, %4};"
                 :: "l"(zp+ 0), "f"(wv*x0.x), "f"(wv*x0.y), "f"(wv*x0.z), "f"(wv*x0.w) : "memory");
    asm volatile("red.global.add.v4.f32 [%0], {%1, %2, %3, %4};"
                 :: "l"(zp+ 4), "f"(wv*x1.x), "f"(wv*x1.y), "f"(wv*x1.z), "f"(wv*x1.w) : "memory");
    asm volatile("red.global.add.v4.f32 [%0], {%1, %2, %3, %4};"
                 :: "l"(zp+ 8), "f"(wv*x2.x), "f"(wv*x2.y), "f"(wv*x2.z), "f"(wv*x2.w) : "memory");
    asm volatile("red.global.add.v4.f32 [%0], {%1, %2, %3, %4};"
                 :: "l"(zp+12), "f"(wv*x3.x), "f"(wv*x3.y), "f"(wv*x3.z), "f"(wv*x3.w) : "memory");
}

template <bool FIRST>
__global__ void spmm_kernel(const int* __restrict__ src,
                            const int* __restrict__ dst,
                            const float* __restrict__ val, int E2, int E) {
    int t = blockIdx.x * blockDim.x + threadIdx.x;
    if (t >= E2) return;
    const float* X = FIRST ? g_Y : g_Z1;
    float*       Z = FIRST ? g_Z1 : g_Z2;
    int e = t * 2;
    if (e + 1 < E) {
        int2   s2 = __ldg((const int2*)src + t);
        int2   d2 = __ldg((const int2*)dst + t);
        float2 v2 = __ldg((const float2*)val + t);
        do_edge<FIRST>(X, Z, s2.x, d2.x, v2.x);
        do_edge<FIRST>(X, Z, s2.y, d2.y, v2.y);
    } else {  // tail (E odd)
        do_edge<FIRST>(X, Z, __ldg(src + e), __ldg(dst + e), __ldg(val + e));
    }
}

// ---------------------------------------------------------------------------
// out[n, 0:40] = log_softmax( Z2[n, 0:16] @ W2[16, 40] )
// One warp per node; fast-math exp/log (MUFU) — rel_err budget is 1e-3.
// ---------------------------------------------------------------------------
__global__ void out_kernel(const float* __restrict__ W2,
                           float* __restrict__ out, int N) {
    __shared__ float w[HID * NC];
    for (int i = threadIdx.x; i < HID * NC; i += blockDim.x) w[i] = W2[i];
    __syncthreads();
    int t = blockIdx.x * blockDim.x + threadIdx.x;
    int n = t >> 5, lane = t & 31;
    if (n >= N) return;
    float z = (lane < HID) ? g_Z2[n * HID + lane] : 0.f;
    float a0 = 0.f, a1 = 0.f;
    int c1 = (lane & 7) + 32;  // valid class only for lane<8; read stays in-bounds
#pragma unroll
    for (int k = 0; k < HID; k++) {
        float zk = __shfl_sync(0xffffffffu, z, k);
        a0 += zk * w[k * NC + lane];
        a1 += zk * w[k * NC + c1];
    }
    float m = (lane < 8) ? fmaxf(a0, a1) : a0;
#pragma unroll
    for (int off = 16; off; off >>= 1)
        m = fmaxf(m, __shfl_xor_sync(0xffffffffu, m, off));
    float s = __expf(a0 - m) + ((lane < 8) ? __expf(a1 - m) : 0.f);
#pragma unroll
    for (int off = 16; off; off >>= 1)
        s += __shfl_xor_sync(0xffffffffu, s, off);
    float lse = m + __logf(s);
    out[n * NC + lane] = a0 - lse;
    if (lane < 8) out[n * NC + 32 + lane] = a1 - lse;
}

// ---------------------------------------------------------------------------
extern "C" void kernel_launch(void* const* d_in, const int* in_sizes, int n_in,
                              void* d_out, int out_size) {
    const float* features = (const float*)d_in[0];
    const int*   esrc     = (const int*)  d_in[1];
    const int*   edst     = (const int*)  d_in[2];
    const float* evals    = (const float*)d_in[3];
    const float* W2       = (const float*)d_in[5];
    const float* W1       = (const float*)d_in[4];
    float*       out      = (float*)d_out;

    int N = in_sizes[0] / IN_DIM;   // 50000
    int E = in_sizes[1];            // 800000
    int E2 = (E + 1) / 2;

    gemm1_kernel<<<(N + 127) / 128, 128>>>(features, W1, N);
    spmm_kernel<true ><<<(E2 + 255) / 256, 256>>>(esrc, edst, evals, E2, E);
    spmm_kernel<false><<<(E2 + 255) / 256, 256>>>(esrc, edst, evals, E2, E);
    out_kernel<<<((long)N * 32 + 255) / 256, 256>>>(W2, out, N);
}

// round 4
// speedup vs baseline: 1.0290x; 1.0290x over previous
#include <cuda_runtime.h>
#include <math.h>

#define MAX_NODES 50000
#define E_MAX     800000
#define IN_DIM 100
#define HID 16
#define NC 40
#define SCAN_BS 1024
#define NB_MAX ((MAX_NODES + SCAN_BS - 1) / SCAN_BS)   // 49

// Scratch (no allocations allowed)
__device__ float g_Y  [MAX_NODES * HID];   // X @ W1
__device__ float g_Z1 [MAX_NODES * HID];   // A @ Y
__device__ float g_Z2 [MAX_NODES * HID];   // A @ relu(Z1)
__device__ int   g_deg [MAX_NODES];
__device__ int   g_off [MAX_NODES + 1];
__device__ int   g_pos [MAX_NODES];
__device__ int   g_bsum[NB_MAX];
__device__ int   g_boff[NB_MAX];
__device__ int2  g_csr [E_MAX];            // (src, bitcast(val)) sorted by dst

// ---------------------------------------------------------------------------
// CSR build: zero degrees -> histogram -> 2-level exclusive scan -> scatter.
// ---------------------------------------------------------------------------
__global__ void zero_deg_kernel(int N) {
    int i = blockIdx.x * blockDim.x + threadIdx.x;
    if (i < N) g_deg[i] = 0;
}

__global__ void hist_kernel(const int* __restrict__ dst, int E) {
    int t = blockIdx.x * blockDim.x + threadIdx.x;
    int base = t * 4;
    if (base + 3 < E) {
        int4 d = __ldg((const int4*)dst + t);
        atomicAdd(&g_deg[d.x], 1); atomicAdd(&g_deg[d.y], 1);
        atomicAdd(&g_deg[d.z], 1); atomicAdd(&g_deg[d.w], 1);
    } else {
        for (int e = base; e < E; e++) atomicAdd(&g_deg[dst[e]], 1);
    }
}

__global__ void scan1_kernel(int N) {   // per-block exclusive scan of g_deg
    __shared__ int s[SCAN_BS];
    int tid = threadIdx.x;
    int i = blockIdx.x * SCAN_BS + tid;
    int v = (i < N) ? g_deg[i] : 0;
    s[tid] = v;
    __syncthreads();
#pragma unroll
    for (int off = 1; off < SCAN_BS; off <<= 1) {
        int t2 = (tid >= off) ? s[tid - off] : 0;
        __syncthreads();
        s[tid] += t2;
        __syncthreads();
    }
    if (i < N) g_off[i] = s[tid] - v;               // exclusive, block-local
    if (tid == SCAN_BS - 1) g_bsum[blockIdx.x] = s[tid];
}

__global__ void scan2_kernel(int NB) {  // scan the 49 block totals
    __shared__ int s[64];
    int tid = threadIdx.x;
    s[tid] = (tid < NB) ? g_bsum[tid] : 0;
    __syncthreads();
    if (tid == 0) {
        int run = 0;
        for (int i = 0; i < NB; i++) { int v = s[i]; s[i] = run; run += v; }
    }
    __syncthreads();
    if (tid < NB) g_boff[tid] = s[tid];
}

__global__ void scan3_kernel(int N, int E) {  // finalize offsets + running pos
    int i = blockIdx.x * blockDim.x + threadIdx.x;
    if (i < N) {
        int o = g_off[i] + g_boff[i >> 10];
        g_off[i] = o;
        g_pos[i] = o;
    }
    if (i == 0) g_off[N] = E;
}

__global__ void scatter_kernel(const int* __restrict__ src,
                               const int* __restrict__ dst,
                               const float* __restrict__ val, int E) {
    int t = blockIdx.x * blockDim.x + threadIdx.x;
    int base = t * 4;
    if (base + 3 < E) {
        int4   s = __ldg((const int4*)src + t);
        int4   d = __ldg((const int4*)dst + t);
        float4 v = __ldg((const float4*)val + t);
        g_csr[atomicAdd(&g_pos[d.x], 1)] = make_int2(s.x, __float_as_int(v.x));
        g_csr[atomicAdd(&g_pos[d.y], 1)] = make_int2(s.y, __float_as_int(v.y));
        g_csr[atomicAdd(&g_pos[d.z], 1)] = make_int2(s.z, __float_as_int(v.z));
        g_csr[atomicAdd(&g_pos[d.w], 1)] = make_int2(s.w, __float_as_int(v.w));
    } else {
        for (int e = base; e < E; e++)
            g_csr[atomicAdd(&g_pos[dst[e]], 1)] = make_int2(src[e], __float_as_int(val[e]));
    }
}

// ---------------------------------------------------------------------------
// Y[n, 0:16] = features[n, 0:100] @ W1[100, 16], one thread per node.
// ---------------------------------------------------------------------------
__global__ void gemm1_kernel(const float* __restrict__ X,
                             const float* __restrict__ W1, int N) {
    __shared__ float4 w[IN_DIM * 4];                  // w[k*4+j4] = W1[k][4j4..]
    for (int i = threadIdx.x; i < IN_DIM * 4; i += blockDim.x)
        w[i] = ((const float4*)W1)[i];
    __syncthreads();
    int n = blockIdx.x * blockDim.x + threadIdx.x;
    if (n >= N) return;

    const float4* xr = (const float4*)(X + (size_t)n * IN_DIM);
    float acc[HID];
#pragma unroll
    for (int j = 0; j < HID; j++) acc[j] = 0.f;
#pragma unroll 5
    for (int k4 = 0; k4 < IN_DIM / 4; k4++) {
        float4 f = __ldg(xr + k4);
        float fk[4] = {f.x, f.y, f.z, f.w};
#pragma unroll
        for (int kk = 0; kk < 4; kk++) {
            int k = k4 * 4 + kk;
#pragma unroll
            for (int j4 = 0; j4 < 4; j4++) {
                float4 wv = w[k * 4 + j4];
                acc[j4*4+0] += fk[kk] * wv.x;
                acc[j4*4+1] += fk[kk] * wv.y;
                acc[j4*4+2] += fk[kk] * wv.z;
                acc[j4*4+3] += fk[kk] * wv.w;
            }
        }
    }
    float4* yo = (float4*)(g_Y + (size_t)n * HID);
#pragma unroll
    for (int j4 = 0; j4 < 4; j4++)
        yo[j4] = make_float4(acc[j4*4+0], acc[j4*4+1], acc[j4*4+2], acc[j4*4+3]);
}

// ---------------------------------------------------------------------------
// Gather SpMM (no atomics): warp per node, lanes = 16 dims x 2 edge slots.
// Z[n] = sum_{e in csr[n]} val_e * (relu?)(X[src_e]); register accumulation,
// one coalesced 64B store. Gather table is L2-resident (3.2MB).
// ---------------------------------------------------------------------------
template <bool FIRST>
__global__ void spmm_gather_kernel(int N) {
    int t = blockIdx.x * blockDim.x + threadIdx.x;
    int n = t >> 5;
    if (n >= N) return;
    int lane = t & 31, j = lane & 15, h = lane >> 4;
    const float* __restrict__ X = FIRST ? g_Y : g_Z1;
    float*       __restrict__ Z = FIRST ? g_Z1 : g_Z2;
    int beg = __ldg(&g_off[n]), end = __ldg(&g_off[n + 1]);
    float acc = 0.f;
    for (int e = beg + h; e < end; e += 2) {
        int2 c = __ldg(&g_csr[e]);                  // uniform per half-warp
        float v = __int_as_float(c.y);
        float x = __ldg(X + (size_t)c.x * HID + j); // 64B coalesced per half-warp
        if (!FIRST) x = fmaxf(x, 0.f);              // fused relu, layer 2
        acc += v * x;
    }
    acc += __shfl_xor_sync(0xffffffffu, acc, 16);
    if (lane < 16) Z[(size_t)n * HID + lane] = acc;
}

// ---------------------------------------------------------------------------
// out[n] = log_softmax( Z2[n, 0:16] @ W2[16, 40] ), one THREAD per node.
// 160 LDS.128 broadcasts + 640 FMA + 40 MUFU exp, all in registers.
// ---------------------------------------------------------------------------
__global__ void out_kernel(const float* __restrict__ W2,
                           float* __restrict__ out, int N) {
    __shared__ float4 w4[HID * (NC / 4)];           // w4[k*10+c4] = W2[k][4c4..]
    for (int i = threadIdx.x; i < HID * (NC / 4); i += blockDim.x)
        w4[i] = ((const float4*)W2)[i];
    __syncthreads();
    int n = blockIdx.x * blockDim.x + threadIdx.x;
    if (n >= N) return;

    const float4* zp = (const float4*)(g_Z2 + (size_t)n * HID);
    float4 zv[4] = {__ldg(zp), __ldg(zp+1), __ldg(zp+2), __ldg(zp+3)};
    float z[HID] = {zv[0].x, zv[0].y, zv[0].z, zv[0].w,
                    zv[1].x, zv[1].y, zv[1].z, zv[1].w,
                    zv[2].x, zv[2].y, zv[2].z, zv[2].w,
                    zv[3].x, zv[3].y, zv[3].z, zv[3].w};
    float acc[NC];
#pragma unroll
    for (int c = 0; c < NC; c++) acc[c] = 0.f;
#pragma unroll
    for (int k = 0; k < HID; k++) {
#pragma unroll
        for (int c4 = 0; c4 < NC / 4; c4++) {
            float4 wv = w4[k * (NC / 4) + c4];
            acc[c4*4+0] += z[k] * wv.x;
            acc[c4*4+1] += z[k] * wv.y;
            acc[c4*4+2] += z[k] * wv.z;
            acc[c4*4+3] += z[k] * wv.w;
        }
    }
    float m = acc[0];
#pragma unroll
    for (int c = 1; c < NC; c++) m = fmaxf(m, acc[c]);
    float s = 0.f;
#pragma unroll
    for (int c = 0; c < NC; c++) s += __expf(acc[c] - m);
    float lse = m + __logf(s);
    float4* o = (float4*)(out + (size_t)n * NC);    // 160B rows, 16B aligned
#pragma unroll
    for (int c4 = 0; c4 < NC / 4; c4++)
        o[c4] = make_float4(acc[c4*4+0]-lse, acc[c4*4+1]-lse,
                            acc[c4*4+2]-lse, acc[c4*4+3]-lse);
}

// ---------------------------------------------------------------------------
extern "C" void kernel_launch(void* const* d_in, const int* in_sizes, int n_in,
                              void* d_out, int out_size) {
    const float* features = (const float*)d_in[0];
    const int*   esrc     = (const int*)  d_in[1];
    const int*   edst     = (const int*)  d_in[2];
    const float* evals    = (const float*)d_in[3];
    const float* W1       = (const float*)d_in[4];
    const float* W2       = (const float*)d_in[5];
    float*       out      = (float*)d_out;

    int N = in_sizes[0] / IN_DIM;   // 50000
    int E = in_sizes[1];            // 800000
    int NB = (N + SCAN_BS - 1) / SCAN_BS;
    int E4 = (E + 3) / 4;

    // CSR build (shared by both SpMM layers)
    zero_deg_kernel<<<(N + 255) / 256, 256>>>(N);
    hist_kernel   <<<(E4 + 255) / 256, 256>>>(edst, E);
    scan1_kernel  <<<NB, SCAN_BS>>>(N);
    scan2_kernel  <<<1, 64>>>(NB);
    scan3_kernel  <<<(N + 255) / 256, 256>>>(N, E);
    scatter_kernel<<<(E4 + 255) / 256, 256>>>(esrc, edst, evals, E);

    // GCN pipeline
    gemm1_kernel<<<(N + 127) / 128, 128>>>(features, W1, N);
    spmm_gather_kernel<true ><<<((long)N * 32 + 255) / 256, 256>>>(N);
    spmm_gather_kernel<false><<<((long)N * 32 + 255) / 256, 256>>>(N);
    out_kernel<<<(N + 127) / 128, 128>>>(W2, out, N);
}